// round 1
// baseline (speedup 1.0000x reference)
#include <cuda_runtime.h>

#define NN   50000
#define NE   800000
#define ETOT (NE + NN)     // edges + self loops
#define FOUT 256           // HEADS * HIDDEN
#define HID  64

// ---------------- scratch (device globals; no allocation allowed) ----------
__device__ float    g_h[NN * FOUT];      // per-layer node features [N, H*C]
__device__ float    g_agg[NN * FOUT];    // unnormalized segment sums
__device__ float    g_asrc[NN * 4];
__device__ float    g_adst[NN * 4];
__device__ unsigned g_max[NN * 4];       // encoded float max
__device__ float    g_sum[NN * 4];       // softmax denominators
__device__ float    g_feat1[NN * HID];   // layer-1 output
__device__ float    g_feat2[NN * HID];   // layer-2 output

// order-preserving float <-> uint mapping for atomicMax
__device__ __forceinline__ unsigned fenc(float f) {
    unsigned u = __float_as_uint(f);
    return (u & 0x80000000u) ? ~u : (u | 0x80000000u);
}
__device__ __forceinline__ float fdec(unsigned u) {
    unsigned b = (u & 0x80000000u) ? (u & 0x7fffffffu) : ~u;
    return __uint_as_float(b);
}
#define ENC_NEG_INF 0x007FFFFFu   // fenc(-inf)

// ---------------- init per layer ------------------------------------------
__global__ void k_init() {
    int i = blockIdx.x * blockDim.x + threadIdx.x;
    if (i < NN * FOUT) g_agg[i] = 0.f;
    if (i < NN * 4) { g_sum[i] = 0.f; g_max[i] = ENC_NEG_INF; }
}

// ---------------- feature GEMM: g_h = X @ W  (W: [FIN, 256]) --------------
template <int FIN>
__global__ void k_gemm(const float* __restrict__ X, const float* __restrict__ W) {
    extern __shared__ float sm[];
    float* Wsh = sm;                 // [FIN][256]
    float* Xs  = sm + FIN * FOUT;    // [FIN][8]  (transposed node tile)
    int t = threadIdx.x;

    for (int i = t; i < FIN * (FOUT / 4); i += 256)
        ((float4*)Wsh)[i] = ((const float4*)W)[i];

    const int nTiles = (NN + 7) / 8;
    for (int tile = blockIdx.x; tile < nTiles; tile += gridDim.x) {
        int n0 = tile * 8;
        __syncthreads();  // protect Xs from previous iteration + W load (1st iter)
        for (int idx = t; idx < 8 * FIN; idx += 256) {
            int k = idx >> 3, i = idx & 7;
            int n = n0 + i;
            Xs[idx] = (n < NN) ? X[n * FIN + k] : 0.f;
        }
        __syncthreads();

        float acc[8];
#pragma unroll
        for (int i = 0; i < 8; i++) acc[i] = 0.f;
#pragma unroll
        for (int k = 0; k < FIN; k++) {
            float  w  = Wsh[k * FOUT + t];
            float4 xa = *(const float4*)&Xs[k * 8];
            float4 xb = *(const float4*)&Xs[k * 8 + 4];
            acc[0] = fmaf(xa.x, w, acc[0]);
            acc[1] = fmaf(xa.y, w, acc[1]);
            acc[2] = fmaf(xa.z, w, acc[2]);
            acc[3] = fmaf(xa.w, w, acc[3]);
            acc[4] = fmaf(xb.x, w, acc[4]);
            acc[5] = fmaf(xb.y, w, acc[5]);
            acc[6] = fmaf(xb.z, w, acc[6]);
            acc[7] = fmaf(xb.w, w, acc[7]);
        }
#pragma unroll
        for (int i = 0; i < 8; i++) {
            int n = n0 + i;
            if (n < NN) g_h[n * FOUT + t] = acc[i];
        }
    }
}

// ---------------- alpha_src / alpha_dst per (node, head) ------------------
__global__ void k_alpha(const float* __restrict__ a_src, const float* __restrict__ a_dst) {
    int i = blockIdx.x * blockDim.x + threadIdx.x;
    if (i >= NN * 4) return;
    int node = i >> 2, hd = i & 3;
    const float4* hp = (const float4*)&g_h[node * FOUT + hd * HID];
    const float4* ap = (const float4*)&a_src[hd * HID];
    const float4* dp = (const float4*)&a_dst[hd * HID];
    float s = 0.f, d = 0.f;
#pragma unroll
    for (int j = 0; j < HID / 4; j++) {
        float4 h4 = hp[j], a4 = ap[j], d4 = dp[j];
        s += h4.x * a4.x + h4.y * a4.y + h4.z * a4.z + h4.w * a4.w;
        d += h4.x * d4.x + h4.y * d4.y + h4.z * d4.z + h4.w * d4.w;
    }
    g_asrc[i] = s;
    g_adst[i] = d;
}

// ---------------- pass A: segment max over edges --------------------------
__global__ void k_edge_max(const int* __restrict__ ei) {
    int e = blockIdx.x * blockDim.x + threadIdx.x;
    if (e >= ETOT) return;
    int src, dst;
    if (e < NE) { src = ei[e]; dst = ei[NE + e]; }
    else        { src = dst = e - NE; }
    float4 as = *(const float4*)&g_asrc[src * 4];
    float4 ad = *(const float4*)&g_adst[dst * 4];
    float e0 = as.x + ad.x; e0 = (e0 >= 0.f) ? e0 : 0.2f * e0;
    float e1 = as.y + ad.y; e1 = (e1 >= 0.f) ? e1 : 0.2f * e1;
    float e2 = as.z + ad.z; e2 = (e2 >= 0.f) ? e2 : 0.2f * e2;
    float e3 = as.w + ad.w; e3 = (e3 >= 0.f) ? e3 : 0.2f * e3;
    atomicMax(&g_max[dst * 4 + 0], fenc(e0));
    atomicMax(&g_max[dst * 4 + 1], fenc(e1));
    atomicMax(&g_max[dst * 4 + 2], fenc(e2));
    atomicMax(&g_max[dst * 4 + 3], fenc(e3));
}

// ---------------- pass B: unnormalized weighted scatter (warp/edge) -------
__global__ void k_edge_agg(const int* __restrict__ ei) {
    int gt = blockIdx.x * blockDim.x + threadIdx.x;
    int gw = gt >> 5, lane = gt & 31;
    if (gw >= ETOT) return;
    int src, dst;
    if (gw < NE) { src = ei[gw]; dst = ei[NE + gw]; }
    else         { src = dst = gw - NE; }

    float w = 0.f;
    if (lane < 4) {
        float a = g_asrc[src * 4 + lane] + g_adst[dst * 4 + lane];
        a = (a >= 0.f) ? a : 0.2f * a;
        float m = fdec(g_max[dst * 4 + lane]);
        w = __expf(a - m);
        atomicAdd(&g_sum[dst * 4 + lane], w);   // compiles to RED (no return)
    }
    float wv = __shfl_sync(0xffffffffu, w, lane >> 3);  // head = lane/8

    const float4* hp = (const float4*)&g_h[src * FOUT + lane * 8];
    float4 v0 = hp[0], v1 = hp[1];
    v0.x *= wv; v0.y *= wv; v0.z *= wv; v0.w *= wv;
    v1.x *= wv; v1.y *= wv; v1.z *= wv; v1.w *= wv;

    float* op = &g_agg[dst * FOUT + lane * 8];
    asm volatile("red.global.add.v4.f32 [%0], {%1,%2,%3,%4};"
                 :: "l"(op), "f"(v0.x), "f"(v0.y), "f"(v0.z), "f"(v0.w) : "memory");
    asm volatile("red.global.add.v4.f32 [%0], {%1,%2,%3,%4};"
                 :: "l"(op + 4), "f"(v1.x), "f"(v1.y), "f"(v1.z), "f"(v1.w) : "memory");
}

// ---------------- normalize, head-mean, bias, ELU -------------------------
__global__ void k_finish(const float* __restrict__ bias, float* __restrict__ out) {
    int i = blockIdx.x * blockDim.x + threadIdx.x;
    if (i >= NN * HID) return;
    int node = i >> 6, c = i & 63;
    float4 s4 = *(const float4*)&g_sum[node * 4];
    const float* ag = &g_agg[node * FOUT + c];
    float v = ag[0]   * (1.f / s4.x)
            + ag[64]  * (1.f / s4.y)
            + ag[128] * (1.f / s4.z)
            + ag[192] * (1.f / s4.w);
    v = 0.25f * v + bias[c];
    out[i] = (v > 0.f) ? v : (__expf(v) - 1.f);
}

// ---------------- scorer MLP: warp per node -------------------------------
__global__ void k_scorer(const float* __restrict__ feat, const float* __restrict__ donor,
                         const float* __restrict__ Ws1, const float* __restrict__ bs1,
                         const float* __restrict__ Ws2, const float* __restrict__ bs2,
                         float* __restrict__ out) {
    __shared__ float sW1[96 * 64];
    __shared__ float sW2[64];
    __shared__ float sB[64];
    __shared__ float sD[32];
    int t = threadIdx.x;
    for (int i = t; i < 96 * 64; i += 256) sW1[i] = Ws1[i];
    if (t < 64) { sW2[t] = Ws2[t]; sB[t] = bs1[t]; }
    if (t < 32) sD[t] = donor[t];
    __syncthreads();

    int warp = t >> 5, lane = t & 31;
    float b2v = bs2[0];
    for (int n = blockIdx.x * 8 + warp; n < NN; n += gridDim.x * 8) {
        float f0 = feat[n * 64 + lane];
        float f1 = feat[n * 64 + 32 + lane];
        float h0 = 0.f, h1 = 0.f;
#pragma unroll
        for (int k = 0; k < 32; k++) {
            float xk = __shfl_sync(0xffffffffu, f0, k);
            h0 = fmaf(xk, sW1[k * 64 + lane], h0);
            h1 = fmaf(xk, sW1[k * 64 + 32 + lane], h1);
        }
#pragma unroll
        for (int k = 0; k < 32; k++) {
            float xk = __shfl_sync(0xffffffffu, f1, k);
            h0 = fmaf(xk, sW1[(k + 32) * 64 + lane], h0);
            h1 = fmaf(xk, sW1[(k + 32) * 64 + 32 + lane], h1);
        }
#pragma unroll
        for (int k = 0; k < 32; k++) {
            float xk = sD[k];
            h0 = fmaf(xk, sW1[(k + 64) * 64 + lane], h0);
            h1 = fmaf(xk, sW1[(k + 64) * 64 + 32 + lane], h1);
        }
        h0 = fmaxf(h0 + sB[lane], 0.f);
        h1 = fmaxf(h1 + sB[lane + 32], 0.f);
        float p = h0 * sW2[lane] + h1 * sW2[lane + 32];
#pragma unroll
        for (int o = 16; o > 0; o >>= 1) p += __shfl_xor_sync(0xffffffffu, p, o);
        if (lane == 0) out[n] = p + b2v;
    }
}

// ---------------- launch ---------------------------------------------------
extern "C" void kernel_launch(void* const* d_in, const int* in_sizes, int n_in,
                              void* d_out, int out_size) {
    const float* x     = (const float*)d_in[0];
    const int*   ei    = (const int*)  d_in[1];
    const float* donor = (const float*)d_in[2];
    const float* W1    = (const float*)d_in[3];
    const float* as1   = (const float*)d_in[4];
    const float* ad1   = (const float*)d_in[5];
    const float* b1    = (const float*)d_in[6];
    const float* W2    = (const float*)d_in[7];
    const float* as2   = (const float*)d_in[8];
    const float* ad2   = (const float*)d_in[9];
    const float* b2    = (const float*)d_in[10];
    const float* Ws1   = (const float*)d_in[11];
    const float* bs1   = (const float*)d_in[12];
    const float* Ws2   = (const float*)d_in[13];
    const float* bs2   = (const float*)d_in[14];
    float* out = (float*)d_out;

    float *feat1, *feat2;
    cudaGetSymbolAddress((void**)&feat1, g_feat1);
    cudaGetSymbolAddress((void**)&feat2, g_feat2);

    const int smem27 = 27 * FOUT * 4 + 8 * 27 * 4;
    const int smem64 = 64 * FOUT * 4 + 8 * 64 * 4;
    cudaFuncSetAttribute(k_gemm<27>, cudaFuncAttributeMaxDynamicSharedMemorySize, smem27);
    cudaFuncSetAttribute(k_gemm<64>, cudaFuncAttributeMaxDynamicSharedMemorySize, smem64);

    const int initGrid   = (NN * FOUT + 255) / 256;
    const int alphaGrid  = (NN * 4 + 255) / 256;
    const int emaxGrid   = (ETOT + 255) / 256;
    const int eaggGrid   = (ETOT * 32 + 255) / 256;
    const int finGrid    = (NN * HID + 255) / 256;

    // ---- layer 1 ----
    k_init<<<initGrid, 256>>>();
    k_gemm<27><<<444, 256, smem27>>>(x, W1);
    k_alpha<<<alphaGrid, 256>>>(as1, ad1);
    k_edge_max<<<emaxGrid, 256>>>(ei);
    k_edge_agg<<<eaggGrid, 256>>>(ei);
    k_finish<<<finGrid, 256>>>(b1, feat1);

    // ---- layer 2 ----
    k_init<<<initGrid, 256>>>();
    k_gemm<64><<<444, 256, smem64>>>(feat1, W2);
    k_alpha<<<alphaGrid, 256>>>(as2, ad2);
    k_edge_max<<<emaxGrid, 256>>>(ei);
    k_edge_agg<<<eaggGrid, 256>>>(ei);
    k_finish<<<finGrid, 256>>>(b2, feat2);

    // ---- scorer ----
    k_scorer<<<1184, 256>>>(feat2, donor, Ws1, bs1, Ws2, bs2, out);
}

// round 2
// speedup vs baseline: 2.1920x; 2.1920x over previous
#include <cuda_runtime.h>

#define NN    50000
#define NE    800000
#define ETOT  (NE + NN)       // edges + self loops
#define FOUT  256             // HEADS * HIDDEN
#define HID   64
#define NPAD  50176           // 196 * 256
#define NBLK  196

// ---------------- scratch (device globals; no allocation allowed) ----------
__device__ float g_h[NN * FOUT];       // per-layer node features [N, H*C]
__device__ float g_asrc[NN * 4];
__device__ float g_adst[NN * 4];
__device__ float g_feat1[NN * HID];
__device__ float g_feat2[NN * HID];

// CSR build (dst-sorted edges; built once per call, reused by both layers)
__device__ int g_cnt[NPAD];
__device__ int g_incl[NPAD];
__device__ int g_bsum[NBLK];
__device__ int g_boff[NBLK];
__device__ int g_row[NN + 1];
__device__ int g_cur[NN];
__device__ int g_es[ETOT];             // src node ids grouped by dst

// ---------------- CSR build ------------------------------------------------
__global__ void k_zero() {
    int i = blockIdx.x * blockDim.x + threadIdx.x;
    if (i < NPAD) g_cnt[i] = 0;
}

__global__ void k_count(const int* __restrict__ ei) {
    int e = blockIdx.x * blockDim.x + threadIdx.x;
    if (e >= ETOT) return;
    int dst = (e < NE) ? ei[NE + e] : (e - NE);
    atomicAdd(&g_cnt[dst], 1);
}

__global__ void k_scan1() {
    __shared__ int s[256];
    int t = threadIdx.x, i = blockIdx.x * 256 + t;
    int c = g_cnt[i];
    s[t] = c;
    __syncthreads();
#pragma unroll
    for (int off = 1; off < 256; off <<= 1) {
        int v = (t >= off) ? s[t - off] : 0;
        __syncthreads();
        s[t] += v;
        __syncthreads();
    }
    g_incl[i] = s[t];
    if (t == 255) g_bsum[blockIdx.x] = s[255];
}

__global__ void k_scan2() {
    __shared__ int s[256];
    int t = threadIdx.x;
    int v = (t < NBLK) ? g_bsum[t] : 0;
    s[t] = v;
    __syncthreads();
#pragma unroll
    for (int off = 1; off < 256; off <<= 1) {
        int u = (t >= off) ? s[t - off] : 0;
        __syncthreads();
        s[t] += u;
        __syncthreads();
    }
    if (t < NBLK) g_boff[t] = s[t] - v;   // exclusive
}

__global__ void k_scan3() {
    int i = blockIdx.x * blockDim.x + threadIdx.x;
    if (i >= NN) return;
    int inc = g_incl[i] + g_boff[i >> 8];
    g_row[i + 1] = inc;
    g_cur[i] = inc - g_cnt[i];
    if (i == 0) g_row[0] = 0;
}

__global__ void k_scatter(const int* __restrict__ ei) {
    int e = blockIdx.x * blockDim.x + threadIdx.x;
    if (e >= ETOT) return;
    int src, dst;
    if (e < NE) { src = ei[e]; dst = ei[NE + e]; }
    else        { src = dst = e - NE; }
    int pos = atomicAdd(&g_cur[dst], 1);
    g_es[pos] = src;
}

// ---------------- feature GEMM: g_h = X @ W  (W: [FIN, 256]) --------------
template <int FIN>
__global__ void k_gemm(const float* __restrict__ X, const float* __restrict__ W) {
    extern __shared__ float sm[];
    float* Wsh = sm;                 // [FIN][256]
    float* Xs  = sm + FIN * FOUT;    // [FIN][8]
    int t = threadIdx.x;

    for (int i = t; i < FIN * (FOUT / 4); i += 256)
        ((float4*)Wsh)[i] = ((const float4*)W)[i];

    const int nTiles = (NN + 7) / 8;
    for (int tile = blockIdx.x; tile < nTiles; tile += gridDim.x) {
        int n0 = tile * 8;
        __syncthreads();
        for (int idx = t; idx < 8 * FIN; idx += 256) {
            int k = idx >> 3, i = idx & 7;
            int n = n0 + i;
            Xs[idx] = (n < NN) ? X[n * FIN + k] : 0.f;
        }
        __syncthreads();

        float acc[8];
#pragma unroll
        for (int i = 0; i < 8; i++) acc[i] = 0.f;
#pragma unroll
        for (int k = 0; k < FIN; k++) {
            float  w  = Wsh[k * FOUT + t];
            float4 xa = *(const float4*)&Xs[k * 8];
            float4 xb = *(const float4*)&Xs[k * 8 + 4];
            acc[0] = fmaf(xa.x, w, acc[0]);
            acc[1] = fmaf(xa.y, w, acc[1]);
            acc[2] = fmaf(xa.z, w, acc[2]);
            acc[3] = fmaf(xa.w, w, acc[3]);
            acc[4] = fmaf(xb.x, w, acc[4]);
            acc[5] = fmaf(xb.y, w, acc[5]);
            acc[6] = fmaf(xb.z, w, acc[6]);
            acc[7] = fmaf(xb.w, w, acc[7]);
        }
#pragma unroll
        for (int i = 0; i < 8; i++) {
            int n = n0 + i;
            if (n < NN) g_h[n * FOUT + t] = acc[i];
        }
    }
}

// ---------------- alpha_src / alpha_dst per (node, head) ------------------
__global__ void k_alpha(const float* __restrict__ a_src, const float* __restrict__ a_dst) {
    int i = blockIdx.x * blockDim.x + threadIdx.x;
    if (i >= NN * 4) return;
    int node = i >> 2, hd = i & 3;
    const float4* hp = (const float4*)&g_h[node * FOUT + hd * HID];
    const float4* ap = (const float4*)&a_src[hd * HID];
    const float4* dp = (const float4*)&a_dst[hd * HID];
    float s = 0.f, d = 0.f;
#pragma unroll
    for (int j = 0; j < HID / 4; j++) {
        float4 h4 = hp[j], a4 = ap[j], d4 = dp[j];
        s += h4.x * a4.x + h4.y * a4.y + h4.z * a4.z + h4.w * a4.w;
        d += h4.x * d4.x + h4.y * d4.y + h4.z * d4.z + h4.w * d4.w;
    }
    g_asrc[i] = s;
    g_adst[i] = d;
}

// ---------------- fused softmax-aggregate + normalize + mean + ELU --------
// one warp per destination node; edges contiguous in g_es[row[n]..row[n+1])
__global__ void __launch_bounds__(256) k_agg(const float* __restrict__ bias,
                                             float* __restrict__ outf) {
    int gw = (blockIdx.x * blockDim.x + threadIdx.x) >> 5;
    int lane = threadIdx.x & 31;
    if (gw >= NN) return;
    int n = gw;
    int beg = g_row[n], end = g_row[n + 1];
    float4 ad4 = *(const float4*)&g_adst[n * 4];

    // pass 1: per-head max over this node's incoming edges
    float m0 = -1e30f, m1 = -1e30f, m2 = -1e30f, m3 = -1e30f;
    for (int i = beg + lane; i < end; i += 32) {
        int s = g_es[i];
        float4 as = *(const float4*)&g_asrc[s * 4];
        float e0 = as.x + ad4.x; e0 = (e0 >= 0.f) ? e0 : 0.2f * e0;
        float e1 = as.y + ad4.y; e1 = (e1 >= 0.f) ? e1 : 0.2f * e1;
        float e2 = as.z + ad4.z; e2 = (e2 >= 0.f) ? e2 : 0.2f * e2;
        float e3 = as.w + ad4.w; e3 = (e3 >= 0.f) ? e3 : 0.2f * e3;
        m0 = fmaxf(m0, e0); m1 = fmaxf(m1, e1);
        m2 = fmaxf(m2, e2); m3 = fmaxf(m3, e3);
    }
#pragma unroll
    for (int o = 16; o > 0; o >>= 1) {
        m0 = fmaxf(m0, __shfl_xor_sync(0xffffffffu, m0, o));
        m1 = fmaxf(m1, __shfl_xor_sync(0xffffffffu, m1, o));
        m2 = fmaxf(m2, __shfl_xor_sync(0xffffffffu, m2, o));
        m3 = fmaxf(m3, __shfl_xor_sync(0xffffffffu, m3, o));
    }

    int head = lane >> 3;
    float mh  = (head == 0) ? m0 : (head == 1) ? m1 : (head == 2) ? m2 : m3;
    float adh = (head == 0) ? ad4.x : (head == 1) ? ad4.y : (head == 2) ? ad4.z : ad4.w;

    // pass 2: weighted accumulate; lane owns comps [lane*8, lane*8+8) of 256
    float4 a0 = {0.f, 0.f, 0.f, 0.f}, a1 = {0.f, 0.f, 0.f, 0.f};
    float wsum = 0.f;
    const float4* h4 = (const float4*)g_h;
    for (int i = beg; i < end; i++) {
        int s = g_es[i];
        float a = __ldg(&g_asrc[s * 4 + head]) + adh;
        a = (a >= 0.f) ? a : 0.2f * a;
        float w = __expf(a - mh);
        wsum += w;
        const float4* hp = h4 + (size_t)s * 64 + lane * 2;
        float4 v0 = hp[0], v1 = hp[1];
        a0.x = fmaf(w, v0.x, a0.x); a0.y = fmaf(w, v0.y, a0.y);
        a0.z = fmaf(w, v0.z, a0.z); a0.w = fmaf(w, v0.w, a0.w);
        a1.x = fmaf(w, v1.x, a1.x); a1.y = fmaf(w, v1.y, a1.y);
        a1.z = fmaf(w, v1.z, a1.z); a1.w = fmaf(w, v1.w, a1.w);
    }

    float nrm = 1.f / wsum;
    a0.x *= nrm; a0.y *= nrm; a0.z *= nrm; a0.w *= nrm;
    a1.x *= nrm; a1.y *= nrm; a1.z *= nrm; a1.w *= nrm;

    // head sum across lanes {L, L^8, L^16, L^24} (head bits are lane bits 3,4)
#pragma unroll
    for (int o = 8; o <= 16; o <<= 1) {
        a0.x += __shfl_xor_sync(0xffffffffu, a0.x, o);
        a0.y += __shfl_xor_sync(0xffffffffu, a0.y, o);
        a0.z += __shfl_xor_sync(0xffffffffu, a0.z, o);
        a0.w += __shfl_xor_sync(0xffffffffu, a0.w, o);
        a1.x += __shfl_xor_sync(0xffffffffu, a1.x, o);
        a1.y += __shfl_xor_sync(0xffffffffu, a1.y, o);
        a1.z += __shfl_xor_sync(0xffffffffu, a1.z, o);
        a1.w += __shfl_xor_sync(0xffffffffu, a1.w, o);
    }

    if (lane < 8) {
        float4 b0 = *(const float4*)&bias[lane * 8];
        float4 b1 = *(const float4*)&bias[lane * 8 + 4];
        float v;
        float4 o0, o1;
        v = 0.25f * a0.x + b0.x; o0.x = (v > 0.f) ? v : (__expf(v) - 1.f);
        v = 0.25f * a0.y + b0.y; o0.y = (v > 0.f) ? v : (__expf(v) - 1.f);
        v = 0.25f * a0.z + b0.z; o0.z = (v > 0.f) ? v : (__expf(v) - 1.f);
        v = 0.25f * a0.w + b0.w; o0.w = (v > 0.f) ? v : (__expf(v) - 1.f);
        v = 0.25f * a1.x + b1.x; o1.x = (v > 0.f) ? v : (__expf(v) - 1.f);
        v = 0.25f * a1.y + b1.y; o1.y = (v > 0.f) ? v : (__expf(v) - 1.f);
        v = 0.25f * a1.z + b1.z; o1.z = (v > 0.f) ? v : (__expf(v) - 1.f);
        v = 0.25f * a1.w + b1.w; o1.w = (v > 0.f) ? v : (__expf(v) - 1.f);
        float4* op = (float4*)&outf[n * HID + lane * 8];
        op[0] = o0;
        op[1] = o1;
    }
}

// ---------------- scorer MLP: warp per node -------------------------------
__global__ void k_scorer(const float* __restrict__ feat, const float* __restrict__ donor,
                         const float* __restrict__ Ws1, const float* __restrict__ bs1,
                         const float* __restrict__ Ws2, const float* __restrict__ bs2,
                         float* __restrict__ out) {
    __shared__ float sW1[96 * 64];
    __shared__ float sW2[64];
    __shared__ float sB[64];
    __shared__ float sD[32];
    int t = threadIdx.x;
    for (int i = t; i < 96 * 64; i += 256) sW1[i] = Ws1[i];
    if (t < 64) { sW2[t] = Ws2[t]; sB[t] = bs1[t]; }
    if (t < 32) sD[t] = donor[t];
    __syncthreads();

    int warp = t >> 5, lane = t & 31;
    float b2v = bs2[0];
    for (int n = blockIdx.x * 8 + warp; n < NN; n += gridDim.x * 8) {
        float f0 = feat[n * 64 + lane];
        float f1 = feat[n * 64 + 32 + lane];
        float h0 = 0.f, h1 = 0.f;
#pragma unroll
        for (int k = 0; k < 32; k++) {
            float xk = __shfl_sync(0xffffffffu, f0, k);
            h0 = fmaf(xk, sW1[k * 64 + lane], h0);
            h1 = fmaf(xk, sW1[k * 64 + 32 + lane], h1);
        }
#pragma unroll
        for (int k = 0; k < 32; k++) {
            float xk = __shfl_sync(0xffffffffu, f1, k);
            h0 = fmaf(xk, sW1[(k + 32) * 64 + lane], h0);
            h1 = fmaf(xk, sW1[(k + 32) * 64 + 32 + lane], h1);
        }
#pragma unroll
        for (int k = 0; k < 32; k++) {
            float xk = sD[k];
            h0 = fmaf(xk, sW1[(k + 64) * 64 + lane], h0);
            h1 = fmaf(xk, sW1[(k + 64) * 64 + 32 + lane], h1);
        }
        h0 = fmaxf(h0 + sB[lane], 0.f);
        h1 = fmaxf(h1 + sB[lane + 32], 0.f);
        float p = h0 * sW2[lane] + h1 * sW2[lane + 32];
#pragma unroll
        for (int o = 16; o > 0; o >>= 1) p += __shfl_xor_sync(0xffffffffu, p, o);
        if (lane == 0) out[n] = p + b2v;
    }
}

// ---------------- launch ---------------------------------------------------
extern "C" void kernel_launch(void* const* d_in, const int* in_sizes, int n_in,
                              void* d_out, int out_size) {
    const float* x     = (const float*)d_in[0];
    const int*   ei    = (const int*)  d_in[1];
    const float* donor = (const float*)d_in[2];
    const float* W1    = (const float*)d_in[3];
    const float* as1   = (const float*)d_in[4];
    const float* ad1   = (const float*)d_in[5];
    const float* b1    = (const float*)d_in[6];
    const float* W2    = (const float*)d_in[7];
    const float* as2   = (const float*)d_in[8];
    const float* ad2   = (const float*)d_in[9];
    const float* b2    = (const float*)d_in[10];
    const float* Ws1   = (const float*)d_in[11];
    const float* bs1   = (const float*)d_in[12];
    const float* Ws2   = (const float*)d_in[13];
    const float* bs2   = (const float*)d_in[14];
    float* out = (float*)d_out;

    float *feat1, *feat2;
    cudaGetSymbolAddress((void**)&feat1, g_feat1);
    cudaGetSymbolAddress((void**)&feat2, g_feat2);

    const int smem27 = 27 * FOUT * 4 + 8 * 27 * 4;
    const int smem64 = 64 * FOUT * 4 + 8 * 64 * 4;
    cudaFuncSetAttribute(k_gemm<27>, cudaFuncAttributeMaxDynamicSharedMemorySize, smem27);
    cudaFuncSetAttribute(k_gemm<64>, cudaFuncAttributeMaxDynamicSharedMemorySize, smem64);

    const int alphaGrid = (NN * 4 + 255) / 256;
    const int edgeGrid  = (ETOT + 255) / 256;
    const int aggGrid   = (NN + 7) / 8;          // warp per node, 8 warps/block
    const int scan3Grid = (NN + 255) / 256;

    // ---- CSR build (edge structure is shared by both layers) ----
    k_zero<<<NBLK, 256>>>();
    k_count<<<edgeGrid, 256>>>(ei);
    k_scan1<<<NBLK, 256>>>();
    k_scan2<<<1, 256>>>();
    k_scan3<<<scan3Grid, 256>>>();
    k_scatter<<<edgeGrid, 256>>>(ei);

    // ---- layer 1 ----
    k_gemm<27><<<444, 256, smem27>>>(x, W1);
    k_alpha<<<alphaGrid, 256>>>(as1, ad1);
    k_agg<<<aggGrid, 256>>>(b1, feat1);

    // ---- layer 2 ----
    k_gemm<64><<<444, 256, smem64>>>(feat1, W2);
    k_alpha<<<alphaGrid, 256>>>(as2, ad2);
    k_agg<<<aggGrid, 256>>>(b2, feat2);

    // ---- scorer ----
    k_scorer<<<1184, 256>>>(feat2, donor, Ws1, bs1, Ws2, bs2, out);
}

// round 3
// speedup vs baseline: 2.3406x; 1.0678x over previous
#include <cuda_runtime.h>
#include <cuda_fp16.h>

#define NN    50000
#define NE    800000
#define ETOT  (NE + NN)       // edges + self loops
#define FOUT  256             // HEADS * HIDDEN
#define HID   64
#define NPAD  50176           // 196 * 256
#define NBLK  196

// ---------------- scratch (device globals; no allocation allowed) ----------
__device__ __half g_hh[NN * FOUT];     // per-layer node features, fp16 [N, H*C]
__device__ float  g_asrc[NN * 4];
__device__ float  g_adst[NN * 4];
__device__ float  g_ew[ETOT * 4];      // per-edge attention logits (4 heads)
__device__ float  g_feat1[NN * HID];
__device__ float  g_feat2[NN * HID];

// CSR build (dst-sorted edges; built once per call, reused by both layers)
__device__ int g_cnt[NPAD];
__device__ int g_incl[NPAD];
__device__ int g_bsum[NBLK];
__device__ int g_boff[NBLK];
__device__ int g_row[NN + 1];
__device__ int g_cur[NN];
__device__ int g_es[ETOT];             // src node ids grouped by dst

// ---------------- CSR build ------------------------------------------------
__global__ void k_zero() {
    int i = blockIdx.x * blockDim.x + threadIdx.x;
    if (i < NPAD) g_cnt[i] = 0;
}

__global__ void k_count(const int* __restrict__ ei) {
    int e = blockIdx.x * blockDim.x + threadIdx.x;
    if (e >= ETOT) return;
    int dst = (e < NE) ? ei[NE + e] : (e - NE);
    atomicAdd(&g_cnt[dst], 1);
}

__global__ void k_scan1() {
    __shared__ int s[256];
    int t = threadIdx.x, i = blockIdx.x * 256 + t;
    int c = g_cnt[i];
    s[t] = c;
    __syncthreads();
#pragma unroll
    for (int off = 1; off < 256; off <<= 1) {
        int v = (t >= off) ? s[t - off] : 0;
        __syncthreads();
        s[t] += v;
        __syncthreads();
    }
    g_incl[i] = s[t];
    if (t == 255) g_bsum[blockIdx.x] = s[255];
}

__global__ void k_scan2() {
    __shared__ int s[256];
    int t = threadIdx.x;
    int v = (t < NBLK) ? g_bsum[t] : 0;
    s[t] = v;
    __syncthreads();
#pragma unroll
    for (int off = 1; off < 256; off <<= 1) {
        int u = (t >= off) ? s[t - off] : 0;
        __syncthreads();
        s[t] += u;
        __syncthreads();
    }
    if (t < NBLK) g_boff[t] = s[t] - v;   // exclusive
}

__global__ void k_scan3() {
    int i = blockIdx.x * blockDim.x + threadIdx.x;
    if (i >= NN) return;
    int inc = g_incl[i] + g_boff[i >> 8];
    g_row[i + 1] = inc;
    g_cur[i] = inc - g_cnt[i];
    if (i == 0) g_row[0] = 0;
}

__global__ void k_scatter(const int* __restrict__ ei) {
    int e = blockIdx.x * blockDim.x + threadIdx.x;
    if (e >= ETOT) return;
    int src, dst;
    if (e < NE) { src = ei[e]; dst = ei[NE + e]; }
    else        { src = dst = e - NE; }
    int pos = atomicAdd(&g_cur[dst], 1);
    g_es[pos] = src;
}

// ---------------- feature GEMM: g_hh = fp16(X @ W)  (W: [FIN, 256]) -------
template <int FIN>
__global__ void k_gemm(const float* __restrict__ X, const float* __restrict__ W) {
    extern __shared__ float sm[];
    float* Wsh = sm;                 // [FIN][256]
    float* Xs  = sm + FIN * FOUT;    // [FIN][8]
    int t = threadIdx.x;

    for (int i = t; i < FIN * (FOUT / 4); i += 256)
        ((float4*)Wsh)[i] = ((const float4*)W)[i];

    const int nTiles = (NN + 7) / 8;
    for (int tile = blockIdx.x; tile < nTiles; tile += gridDim.x) {
        int n0 = tile * 8;
        __syncthreads();
        for (int idx = t; idx < 8 * FIN; idx += 256) {
            int k = idx >> 3, i = idx & 7;
            int n = n0 + i;
            Xs[idx] = (n < NN) ? X[n * FIN + k] : 0.f;
        }
        __syncthreads();

        float acc[8];
#pragma unroll
        for (int i = 0; i < 8; i++) acc[i] = 0.f;
#pragma unroll
        for (int k = 0; k < FIN; k++) {
            float  w  = Wsh[k * FOUT + t];
            float4 xa = *(const float4*)&Xs[k * 8];
            float4 xb = *(const float4*)&Xs[k * 8 + 4];
            acc[0] = fmaf(xa.x, w, acc[0]);
            acc[1] = fmaf(xa.y, w, acc[1]);
            acc[2] = fmaf(xa.z, w, acc[2]);
            acc[3] = fmaf(xa.w, w, acc[3]);
            acc[4] = fmaf(xb.x, w, acc[4]);
            acc[5] = fmaf(xb.y, w, acc[5]);
            acc[6] = fmaf(xb.z, w, acc[6]);
            acc[7] = fmaf(xb.w, w, acc[7]);
        }
#pragma unroll
        for (int i = 0; i < 8; i++) {
            int n = n0 + i;
            if (n < NN) g_hh[n * FOUT + t] = __float2half_rn(acc[i]);
        }
    }
}

// ---------------- alpha_src / alpha_dst per (node, head) ------------------
__global__ void k_alpha(const float* __restrict__ a_src, const float* __restrict__ a_dst) {
    int i = blockIdx.x * blockDim.x + threadIdx.x;
    if (i >= NN * 4) return;
    int node = i >> 2, hd = i & 3;
    const __half2* hp = (const __half2*)&g_hh[node * FOUT + hd * HID];
    const float2*  ap = (const float2*)&a_src[hd * HID];
    const float2*  dp = (const float2*)&a_dst[hd * HID];
    float s = 0.f, d = 0.f;
#pragma unroll
    for (int j = 0; j < HID / 2; j++) {
        float2 h2 = __half22float2(hp[j]);
        float2 a2 = ap[j], d2 = dp[j];
        s += h2.x * a2.x + h2.y * a2.y;
        d += h2.x * d2.x + h2.y * d2.y;
    }
    g_asrc[i] = s;
    g_adst[i] = d;
}

// ---------------- fused softmax-aggregate + normalize + mean + ELU --------
// one warp per destination node; edges contiguous in g_es[row[n]..row[n+1])
__device__ __forceinline__ void acc_edge(float w, uint4 u,
                                         float4& a0, float4& a1) {
    float2 f;
    f = __half22float2(*(__half2*)&u.x); a0.x = fmaf(w, f.x, a0.x); a0.y = fmaf(w, f.y, a0.y);
    f = __half22float2(*(__half2*)&u.y); a0.z = fmaf(w, f.x, a0.z); a0.w = fmaf(w, f.y, a0.w);
    f = __half22float2(*(__half2*)&u.z); a1.x = fmaf(w, f.x, a1.x); a1.y = fmaf(w, f.y, a1.y);
    f = __half22float2(*(__half2*)&u.w); a1.z = fmaf(w, f.x, a1.z); a1.w = fmaf(w, f.y, a1.w);
}

__global__ void __launch_bounds__(256) k_agg(const float* __restrict__ bias,
                                             float* __restrict__ outf) {
    int gw = (blockIdx.x * blockDim.x + threadIdx.x) >> 5;
    int lane = threadIdx.x & 31;
    if (gw >= NN) return;
    int n = gw;
    int beg = g_row[n], end = g_row[n + 1];
    float4 ad4 = *(const float4*)&g_adst[n * 4];

    // pass 1: per-head leaky logits -> g_ew, and per-head max
    float m0 = -1e30f, m1 = -1e30f, m2 = -1e30f, m3 = -1e30f;
    for (int i = beg + lane; i < end; i += 32) {
        int s = g_es[i];
        float4 as = *(const float4*)&g_asrc[s * 4];
        float e0 = as.x + ad4.x; e0 = (e0 >= 0.f) ? e0 : 0.2f * e0;
        float e1 = as.y + ad4.y; e1 = (e1 >= 0.f) ? e1 : 0.2f * e1;
        float e2 = as.z + ad4.z; e2 = (e2 >= 0.f) ? e2 : 0.2f * e2;
        float e3 = as.w + ad4.w; e3 = (e3 >= 0.f) ? e3 : 0.2f * e3;
        *(float4*)&g_ew[i * 4] = make_float4(e0, e1, e2, e3);
        m0 = fmaxf(m0, e0); m1 = fmaxf(m1, e1);
        m2 = fmaxf(m2, e2); m3 = fmaxf(m3, e3);
    }
#pragma unroll
    for (int o = 16; o > 0; o >>= 1) {
        m0 = fmaxf(m0, __shfl_xor_sync(0xffffffffu, m0, o));
        m1 = fmaxf(m1, __shfl_xor_sync(0xffffffffu, m1, o));
        m2 = fmaxf(m2, __shfl_xor_sync(0xffffffffu, m2, o));
        m3 = fmaxf(m3, __shfl_xor_sync(0xffffffffu, m3, o));
    }

    int head = lane >> 3;
    float mh = (head == 0) ? m0 : (head == 1) ? m1 : (head == 2) ? m2 : m3;

    // ensure pass-1 g_ew stores are visible to all lanes' reads below
    __syncwarp();

    // pass 2: weighted accumulate; lane owns comps [lane*8, lane*8+8) of 256
    float4 a0 = {0.f, 0.f, 0.f, 0.f}, a1 = {0.f, 0.f, 0.f, 0.f};
    float wsum = 0.f;
    const uint4* h16 = (const uint4*)g_hh;   // 8 halves per uint4; 32 per row
    int i = beg;
    for (; i + 2 <= end; i += 2) {
        int s0 = g_es[i], s1 = g_es[i + 1];
        float w0 = __expf(g_ew[i * 4 + head] - mh);
        float w1 = __expf(g_ew[(i + 1) * 4 + head] - mh);
        uint4 u0 = h16[s0 * 32 + lane];
        uint4 u1 = h16[s1 * 32 + lane];
        wsum += w0 + w1;
        acc_edge(w0, u0, a0, a1);
        acc_edge(w1, u1, a0, a1);
    }
    if (i < end) {
        int s0 = g_es[i];
        float w0 = __expf(g_ew[i * 4 + head] - mh);
        uint4 u0 = h16[s0 * 32 + lane];
        wsum += w0;
        acc_edge(w0, u0, a0, a1);
    }

    float nrm = 1.f / wsum;
    a0.x *= nrm; a0.y *= nrm; a0.z *= nrm; a0.w *= nrm;
    a1.x *= nrm; a1.y *= nrm; a1.z *= nrm; a1.w *= nrm;

    // head sum across lanes {L, L^8, L^16, L^24} (head bits are lane bits 3,4)
#pragma unroll
    for (int o = 8; o <= 16; o <<= 1) {
        a0.x += __shfl_xor_sync(0xffffffffu, a0.x, o);
        a0.y += __shfl_xor_sync(0xffffffffu, a0.y, o);
        a0.z += __shfl_xor_sync(0xffffffffu, a0.z, o);
        a0.w += __shfl_xor_sync(0xffffffffu, a0.w, o);
        a1.x += __shfl_xor_sync(0xffffffffu, a1.x, o);
        a1.y += __shfl_xor_sync(0xffffffffu, a1.y, o);
        a1.z += __shfl_xor_sync(0xffffffffu, a1.z, o);
        a1.w += __shfl_xor_sync(0xffffffffu, a1.w, o);
    }

    if (lane < 8) {
        float4 b0 = *(const float4*)&bias[lane * 8];
        float4 b1 = *(const float4*)&bias[lane * 8 + 4];
        float v;
        float4 o0, o1;
        v = 0.25f * a0.x + b0.x; o0.x = (v > 0.f) ? v : (__expf(v) - 1.f);
        v = 0.25f * a0.y + b0.y; o0.y = (v > 0.f) ? v : (__expf(v) - 1.f);
        v = 0.25f * a0.z + b0.z; o0.z = (v > 0.f) ? v : (__expf(v) - 1.f);
        v = 0.25f * a0.w + b0.w; o0.w = (v > 0.f) ? v : (__expf(v) - 1.f);
        v = 0.25f * a1.x + b1.x; o1.x = (v > 0.f) ? v : (__expf(v) - 1.f);
        v = 0.25f * a1.y + b1.y; o1.y = (v > 0.f) ? v : (__expf(v) - 1.f);
        v = 0.25f * a1.z + b1.z; o1.z = (v > 0.f) ? v : (__expf(v) - 1.f);
        v = 0.25f * a1.w + b1.w; o1.w = (v > 0.f) ? v : (__expf(v) - 1.f);
        float4* op = (float4*)&outf[n * HID + lane * 8];
        op[0] = o0;
        op[1] = o1;
    }
}

// ---------------- scorer MLP: warp per node -------------------------------
__global__ void k_scorer(const float* __restrict__ feat, const float* __restrict__ donor,
                         const float* __restrict__ Ws1, const float* __restrict__ bs1,
                         const float* __restrict__ Ws2, const float* __restrict__ bs2,
                         float* __restrict__ out) {
    __shared__ float sW1[96 * 64];
    __shared__ float sW2[64];
    __shared__ float sB[64];
    __shared__ float sD[32];
    int t = threadIdx.x;
    for (int i = t; i < 96 * 64; i += 256) sW1[i] = Ws1[i];
    if (t < 64) { sW2[t] = Ws2[t]; sB[t] = bs1[t]; }
    if (t < 32) sD[t] = donor[t];
    __syncthreads();

    int warp = t >> 5, lane = t & 31;
    float b2v = bs2[0];
    for (int n = blockIdx.x * 8 + warp; n < NN; n += gridDim.x * 8) {
        float f0 = feat[n * 64 + lane];
        float f1 = feat[n * 64 + 32 + lane];
        float h0 = 0.f, h1 = 0.f;
#pragma unroll
        for (int k = 0; k < 32; k++) {
            float xk = __shfl_sync(0xffffffffu, f0, k);
            h0 = fmaf(xk, sW1[k * 64 + lane], h0);
            h1 = fmaf(xk, sW1[k * 64 + 32 + lane], h1);
        }
#pragma unroll
        for (int k = 0; k < 32; k++) {
            float xk = __shfl_sync(0xffffffffu, f1, k);
            h0 = fmaf(xk, sW1[(k + 32) * 64 + lane], h0);
            h1 = fmaf(xk, sW1[(k + 32) * 64 + 32 + lane], h1);
        }
#pragma unroll
        for (int k = 0; k < 32; k++) {
            float xk = sD[k];
            h0 = fmaf(xk, sW1[(k + 64) * 64 + lane], h0);
            h1 = fmaf(xk, sW1[(k + 64) * 64 + 32 + lane], h1);
        }
        h0 = fmaxf(h0 + sB[lane], 0.f);
        h1 = fmaxf(h1 + sB[lane + 32], 0.f);
        float p = h0 * sW2[lane] + h1 * sW2[lane + 32];
#pragma unroll
        for (int o = 16; o > 0; o >>= 1) p += __shfl_xor_sync(0xffffffffu, p, o);
        if (lane == 0) out[n] = p + b2v;
    }
}

// ---------------- launch ---------------------------------------------------
extern "C" void kernel_launch(void* const* d_in, const int* in_sizes, int n_in,
                              void* d_out, int out_size) {
    const float* x     = (const float*)d_in[0];
    const int*   ei    = (const int*)  d_in[1];
    const float* donor = (const float*)d_in[2];
    const float* W1    = (const float*)d_in[3];
    const float* as1   = (const float*)d_in[4];
    const float* ad1   = (const float*)d_in[5];
    const float* b1    = (const float*)d_in[6];
    const float* W2    = (const float*)d_in[7];
    const float* as2   = (const float*)d_in[8];
    const float* ad2   = (const float*)d_in[9];
    const float* b2    = (const float*)d_in[10];
    const float* Ws1   = (const float*)d_in[11];
    const float* bs1   = (const float*)d_in[12];
    const float* Ws2   = (const float*)d_in[13];
    const float* bs2   = (const float*)d_in[14];
    float* out = (float*)d_out;

    float *feat1, *feat2;
    cudaGetSymbolAddress((void**)&feat1, g_feat1);
    cudaGetSymbolAddress((void**)&feat2, g_feat2);

    const int smem27 = 27 * FOUT * 4 + 8 * 27 * 4;
    const int smem64 = 64 * FOUT * 4 + 8 * 64 * 4;
    cudaFuncSetAttribute(k_gemm<27>, cudaFuncAttributeMaxDynamicSharedMemorySize, smem27);
    cudaFuncSetAttribute(k_gemm<64>, cudaFuncAttributeMaxDynamicSharedMemorySize, smem64);

    const int alphaGrid = (NN * 4 + 255) / 256;
    const int edgeGrid  = (ETOT + 255) / 256;
    const int aggGrid   = (NN + 7) / 8;          // warp per node, 8 warps/block
    const int scan3Grid = (NN + 255) / 256;

    // ---- CSR build (edge structure is shared by both layers) ----
    k_zero<<<NBLK, 256>>>();
    k_count<<<edgeGrid, 256>>>(ei);
    k_scan1<<<NBLK, 256>>>();
    k_scan2<<<1, 256>>>();
    k_scan3<<<scan3Grid, 256>>>();
    k_scatter<<<edgeGrid, 256>>>(ei);

    // ---- layer 1 ----
    k_gemm<27><<<444, 256, smem27>>>(x, W1);
    k_alpha<<<alphaGrid, 256>>>(as1, ad1);
    k_agg<<<aggGrid, 256>>>(b1, feat1);

    // ---- layer 2 ----
    k_gemm<64><<<444, 256, smem64>>>(feat1, W2);
    k_alpha<<<alphaGrid, 256>>>(as2, ad2);
    k_agg<<<aggGrid, 256>>>(b2, feat2);

    // ---- scorer ----
    k_scorer<<<1184, 256>>>(feat2, donor, Ws1, bs1, Ws2, bs2, out);
}